// round 14
// baseline (speedup 1.0000x reference)
#include <cuda_runtime.h>
#include <math.h>

// Spectral solution of 1000 masked-Jacobi steps on 512x512, ONE persistent
// kernel, DST parity butterfly (see R13 header for the math).
// Round 14: LATENCY ENGINEERING on the inter-stage chain:
//  (1) symmetric ONE-HOP grid barrier (all CTAs post flags, all poll all;
//      replaces the two-hop CTA0-aggregated barrier)
//  (2) barrier moved INSIDE gemm_tile, issued AFTER the constant (basis)
//      operand's LDGs -> the barrier wait hides that load latency
//      (G2: A=S const; G3: B=S const; G4: A=STe/STo const)
//  (3) W-weight computation moved after G1 (off the bar1->G1 critical path;
//      still ordered before G3's reads by barriers 2+3)
// Everything else identical to R13 (27.8us).

#define NCTA 128
#define TPB  512
#define HTPB 256
#define GT   (NCTA * TPB)
#define SMS  68                  // smem row stride: 272B = 17*16B
#define CHUNK (16 * SMS)

__device__ float g_Be [512 * 256];      // B even columns
__device__ float g_Bo [512 * 256];      // B odd columns
__device__ float g_S  [128 * 512];      // S[m][c] = sin(pi I(m)(c+1)/511)
__device__ float g_STe[256 * 64];       // STe[k2][i-1] = s_i at grid col 2k2
__device__ float g_STo[256 * 64];       // STo[k2][i-1] = s_i at grid col 2k2+1
__device__ float g_PE [8 * 512 * 64];   // G1 even-parity K-partials
__device__ float g_PO [8 * 512 * 64];   // G1 odd-parity  K-partials
__device__ float g_Cq [16 * 128 * 128]; // G2 K-partials
__device__ float g_U  [4 * 128 * 512];  // G3 K-partials
__device__ float g_W  [128 * 128];      // signed spectral weights
__device__ float2 g_cds[64];            // cos(pi*i/511), i=1..64, double-single
__device__ unsigned g_bars[NCTA];       // symmetric barrier epoch flags

__device__ __forceinline__ unsigned ld_acq(const unsigned* p) {
    unsigned v;
    asm volatile("ld.acquire.gpu.u32 %0, [%1];" : "=r"(v) : "l"(p) : "memory");
    return v;
}
__device__ __forceinline__ void st_rel(unsigned* p, unsigned v) {
    asm volatile("st.release.gpu.u32 [%0], %1;" :: "l"(p), "r"(v) : "memory");
}
__device__ __forceinline__ void bar_named(int id) {
    asm volatile("bar.sync %0, %1;" :: "r"(id), "r"(HTPB) : "memory");
}
__device__ __forceinline__ int modeI(int m) { return (m < 64) ? (m + 1) : (574 - m); }

// Symmetric one-hop grid barrier: each CTA posts its epoch; threads 0..127
// each poll one CTA's flag; syncthreads closes the acquire.
__device__ __forceinline__ void grid_bar(unsigned ep) {
    __syncthreads();
    const int tid = threadIdx.x;
    if (tid == 0) st_rel(&g_bars[blockIdx.x], ep);
    if (tid < NCTA)
        while (ld_acq(&g_bars[tid]) < ep) { }
    __syncthreads();
}

// ---- double-single (two-float) helpers ----
struct DS { float hi, lo; };
__device__ __forceinline__ DS ds_renorm(float s, float e) {
    float hi = s + e;
    float lo = e - (hi - s);
    return DS{hi, lo};
}
__device__ __forceinline__ DS ds_add(DS a, DS b) {
    float s = a.hi + b.hi;
    float v = s - a.hi;
    float e = (a.hi - (s - v)) + (b.hi - v);
    return ds_renorm(s, (e + a.lo) + b.lo);
}
__device__ __forceinline__ DS ds_mul(DS a, DS b) {
    float p = a.hi * b.hi;
    float e = fmaf(a.hi, b.hi, -p);
    e = fmaf(a.hi, b.lo, e);
    e = fmaf(a.lo, b.hi, e);
    return ds_renorm(p, e);
}

// AF: 0 plain A; 1 = (Cq0+..+Cq15) ⊙ W (lda=128)
// BF: 0 plain B; 1 = sum8(PE)+sgn*sum8(PO); 2 = sum4(U_low)+sgn*sum4(U_high)
// STM: 0 plain store; 1 = strided shifted store (row 2*k2+1+eo, col c+1)
// CPRE: 0 = barrier first; 1 = A const (loadA, barrier, loadB);
//       2 = B const (loadB, barrier, loadA)
template<int BM, int TM, int AF, int BF, int STM, int CPRE>
__device__ void gemm_tile(const float* __restrict__ A, int lda,
                          const float* __restrict__ Bop, int ldb,
                          float* __restrict__ Cout, int ldc,
                          int mT, int nT, int kbase, int Klen,
                          float sgn, int eo, unsigned ep,
                          int tid, int barid,
                          float* __restrict__ As, float* __restrict__ Bs) {
    const int tx = tid & 15, ty = tid >> 4;
    const int am = (BM == 64) ? (tid >> 2) : (tid >> 3);
    const int ak = (BM == 64) ? (tid & 3) * 4 : (tid & 7) * 2;
    const int bk = tid >> 4;
    const int bn = (tid & 15) * 2;
    const int nb = (BF == 1) ? ((nT < 64 ? nT : nT - 64) + bn) : 0;

    float4 ra; float2 rb;
    auto loadA = [&](int k0) {
        const int k = kbase + k0 + ak;
        if (AF == 1) {
            const float* p = g_Cq + (mT + am) * 128 + k;
            float2 s = *(const float2*)p;
#pragma unroll
            for (int h = 1; h < 16; h++) {
                float2 c = *(const float2*)(p + h * 16384);
                s.x += c.x; s.y += c.y;
            }
            float2 w = *(const float2*)&g_W[(mT + am) * 128 + k];
            ra.x = s.x * w.x; ra.y = s.y * w.y;
        } else if (BM == 64) {
            ra = *(const float4*)(A + (size_t)(mT + am) * lda + k);
        } else {
            float2 v = *(const float2*)(A + (size_t)(mT + am) * lda + k);
            ra.x = v.x; ra.y = v.y;
        }
    };
    auto loadB = [&](int k0) {
        const int k = kbase + k0 + bk;
        if (BF == 1) {
            const float* pe = g_PE + k * 64 + nb;
            const float* po = g_PO + k * 64 + nb;
            float ex = 0.f, ey = 0.f, ox = 0.f, oy = 0.f;
#pragma unroll
            for (int h = 0; h < 8; h++) {
                float2 e = *(const float2*)(pe + h * 32768);
                float2 o = *(const float2*)(po + h * 32768);
                ex += e.x; ey += e.y; ox += o.x; oy += o.y;
            }
            rb.x = fmaf(sgn, ox, ex); rb.y = fmaf(sgn, oy, ey);
        } else if (BF == 2) {
            const float* pl = g_U + k * 512 + nT + bn;
            float lx = 0.f, ly = 0.f, hx = 0.f, hy = 0.f;
#pragma unroll
            for (int h = 0; h < 4; h++) {
                float2 l  = *(const float2*)(pl + h * 65536);
                float2 hh = *(const float2*)(pl + 64 * 512 + h * 65536);
                lx += l.x; ly += l.y; hx += hh.x; hy += hh.y;
            }
            rb.x = fmaf(sgn, hx, lx); rb.y = fmaf(sgn, hy, ly);
        } else {
            rb = *(const float2*)(Bop + (size_t)k * ldb + nT + bn);
        }
    };
    auto stash = [&](int buf) {
        float* as = As + buf * CHUNK;
        float* bs = Bs + buf * CHUNK;
        as[(ak + 0) * SMS + am] = ra.x;            // A transposed
        as[(ak + 1) * SMS + am] = ra.y;
        if (BM == 64) {
            as[(ak + 2) * SMS + am] = ra.z;
            as[(ak + 3) * SMS + am] = ra.w;
        }
        *(float2*)&bs[bk * SMS + bn] = rb;
    };

    // prologue: const operand issued BEFORE the grid barrier so its LDG
    // latency hides under the barrier wait; data operand after.
    if (CPRE == 1)      { loadA(0); grid_bar(ep); loadB(0); }
    else if (CPRE == 2) { loadB(0); grid_bar(ep); loadA(0); }
    else                { grid_bar(ep); loadA(0); loadB(0); }

    float acc[TM][2];
#pragma unroll
    for (int i = 0; i < TM; i++) { acc[i][0] = 0.0f; acc[i][1] = 0.0f; }

    const int nchunk = Klen / 16;
    stash(0);
    bar_named(barid);

    for (int c = 0; c < nchunk; c++) {
        const float* as = As + (c & 1) * CHUNK;
        const float* bs = Bs + (c & 1) * CHUNK;
        if (c + 1 < nchunk) { loadA((c + 1) * 16); loadB((c + 1) * 16); }
#pragma unroll
        for (int kk = 0; kk < 16; kk++) {
            float a[TM];
            if (TM == 4) {
                float4 v = *(const float4*)&as[kk * SMS + ty * 4];
                a[0] = v.x; a[1] = v.y; a[2] = v.z; a[3] = v.w;
            } else {
                float2 v = *(const float2*)&as[kk * SMS + ty * 2];
                a[0] = v.x; a[1] = v.y;
            }
            float2 b = *(const float2*)&bs[kk * SMS + tx * 2];
#pragma unroll
            for (int i = 0; i < TM; i++) {
                acc[i][0] += a[i] * b.x;
                acc[i][1] += a[i] * b.y;
            }
        }
        if (c + 1 < nchunk) stash((c + 1) & 1);
        bar_named(barid);
    }

    if (STM == 1) {
#pragma unroll
        for (int i = 0; i < TM; i++) {
            int k2 = mT + ty * TM + i;
            if (k2 >= 255) continue;
            int rr = 2 * k2 + 1 + eo;              // +1 output shift
#pragma unroll
            for (int j = 0; j < 2; j++) {
                int c2 = nT + tx * 2 + j;
                if (c2 < 510) Cout[rr * 512 + c2 + 1] = acc[i][j];
            }
        }
    } else {
#pragma unroll
        for (int i = 0; i < TM; i++)
            *(float2*)&Cout[(size_t)(mT + ty * TM + i) * ldc + nT + tx * 2] =
                make_float2(acc[i][0], acc[i][1]);
    }
}

__global__ void __launch_bounds__(TPB, 1)
jacobi_fused(const float* __restrict__ X, const float* __restrict__ Y,
             float* __restrict__ out) {
    __shared__ float sx0[6 * 512];
    __shared__ float As[2 * 2 * CHUNK];            // [half][buf]
    __shared__ float Bs[2 * 2 * CHUNK];
    const int cta = blockIdx.x, tid = threadIdx.x;
    const int gtid = cta * TPB + tid;
    const int half = tid >> 8;
    const int htid = tid & 255;
    const int barid = 1 + half;
    float* myAs = As + half * 2 * CHUNK;
    float* myBs = Bs + half * 2 * CHUNK;
    const unsigned eb = __ldcg(&g_bars[cta]);      // all flags equal at entry
    const int jid = cta * 2 + half;                // 0..255

    // ---- Stage A+B fused ----
    if (gtid < 64) {                               // ONLY fp64: 64 cospi calls
        double c = cospi((double)(gtid + 1) / 511.0);
        float hi = (float)c;
        float lo = (float)(c - (double)hi);
        g_cds[gtid] = make_float2(hi, lo);
    }
    const int r0 = cta * 4;
    int nrows = 512 - r0; if (nrows > 6) nrows = 6;
    for (int i = tid; i < nrows * 512; i += TPB) {
        int lr = i >> 9, j = i & 511;
        int g = (r0 + lr) * 512 + j;
        float dx = X[g] - 0.5f, dy = Y[g] - 0.5f;
        sx0[i] = expf(-50.0f * (dx * dx + dy * dy));
    }
    __syncthreads();
    for (int i = tid; i < 4 * 512; i += TPB) {     // exact stencil, split cols
        int lk = i >> 9, j = i & 511;
        int k = r0 + lk;
        float v = 0.0f;
        if (k < 510 && j < 510)
            v = 0.25f * (((sx0[lk * 512 + j + 1] + sx0[(lk + 2) * 512 + j + 1])
                          + sx0[(lk + 1) * 512 + j]) + sx0[(lk + 1) * 512 + j + 2]);
        if (j & 1) g_Bo[k * 256 + (j >> 1)] = v;
        else       g_Be[k * 256 + (j >> 1)] = v;
    }
    for (int i = gtid; i < 128 * 512; i += GT) {   // S[m][c]
        int m = i >> 9, c = i & 511;
        float v = 0.0f;
        if (c < 510) {
            int a = (modeI(m) * (c + 1)) % 1022;   // exact reduction
            v = sinpif((float)a * (1.0f / 511.0f));
        }
        g_S[i] = v;
    }
    for (int i = gtid; i < 256 * 64; i += GT) {    // STe/STo
        int k2 = i >> 6, ii = (i & 63) + 1;
        float ve = 0.0f, vo = 0.0f;
        if (k2 < 255) {
            int ae = (ii * (2 * k2 + 1)) % 1022;
            ve = sinpif((float)ae * (1.0f / 511.0f));
            int ao = (ii * (2 * k2 + 2)) % 1022;
            vo = sinpif((float)ao * (1.0f / 511.0f));
        }
        g_STe[i] = ve; g_STo[i] = vo;
    }
    for (int i = gtid; i < 2048; i += GT) {        // out boundary
        int e = i >> 9, t = i & 511;
        if      (e == 0) out[t] = 0.0f;
        else if (e == 1) out[511 * 512 + t] = 0.0f;
        else if (e == 2) out[t * 512] = 0.0f;
        else             out[t * 512 + 511] = 0.0f;
    }

    // ---- G1: PE = Be*STe / PO = Bo*STo (bar eb+1 inside, CPRE=0) ----
    {
        int p = jid & 1, t = (jid >> 1) & 15, h = jid >> 5;
        const float* Aop = p ? g_Bo : g_Be;
        const float* Bop = p ? g_STo : g_STe;
        float* Cop = (p ? g_PO : g_PE) + h * 32768;
        gemm_tile<64, 4, 0, 0, 0, 0>(Aop, 256, Bop, 64, Cop, 64,
                                     (t >> 1) * 64, (t & 1) * 32, h * 32, 32,
                                     0.f, 0, eb + 1, htid, barid, myAs, myBs);
    }

    // ---- W in DS fp32, AFTER G1 (off the bar1 critical path; ordered
    //      before G3's reads by barriers eb+2 and eb+3) ----
    for (int i = gtid; i < 128 * 128; i += GT) {
        int m = i >> 7, n = i & 127;
        float2 a2 = g_cds[(m < 64) ? m : (m - 64)];
        float2 b2 = g_cds[(n < 64) ? n : (n - 64)];
        DS cm = (m < 64) ? DS{a2.x, a2.y} : DS{-a2.x, -a2.y};
        DS cn = (n < 64) ? DS{b2.x, b2.y} : DS{-b2.x, -b2.y};
        DS lam = ds_add(cm, cn);
        lam.hi *= 0.5f; lam.lo *= 0.5f;
        DS r{1.0f, 0.0f}, b = lam;
        int e = 999;
        while (e) {
            if (e & 1) r = ds_mul(r, b);
            b = ds_mul(b, b);
            e >>= 1;
        }
        const DS K{1.5318627e-05f, -5.6477107e-13f};   // 4/511^2 split
        r = ds_mul(r, K);
        g_W[i] = r.hi + r.lo;
    }

    // ---- G2: Cq = S * (PE +/- PO fused); A=S const (CPRE=1), bar eb+2 ----
    {
        int t = jid >> 4, h = jid & 15;
        int mT = (t >> 2) * 32, nT = (t & 3) * 32;
        float sgn = (nT < 64) ? 1.0f : -1.0f;
        gemm_tile<32, 2, 0, 1, 0, 1>(g_S, 512, g_PE, 64, g_Cq + h * 16384, 128,
                                     mT, nT, h * 32, 32,
                                     sgn, 0, eb + 2, htid, barid, myAs, myBs);
    }

    // ---- G3: U = ((sum Cq) ⊙ W) * S; B=S const (CPRE=2), bar eb+3 ----
    {
        int t = jid >> 2, h = jid & 3;
        gemm_tile<32, 2, 1, 0, 0, 2>(g_Cq, 128, g_S, 512, g_U + h * 65536, 512,
                                     (t >> 4) * 32, (t & 15) * 32, h * 32, 32,
                                     0.f, 0, eb + 3, htid, barid, myAs, myBs);
    }

    // ---- G4: out_e = STe*(Ul+Uh), out_o = STo*(Ul-Uh); A const, bar eb+4 ----
    {
        int eo = jid >> 7, t = jid & 127;
        const float* Aop = eo ? g_STo : g_STe;
        float sgn = eo ? -1.0f : 1.0f;
        gemm_tile<32, 2, 0, 2, 1, 1>(Aop, 64, g_U, 512, out, 512,
                                     (t >> 4) * 32, (t & 15) * 32, 0, 64,
                                     sgn, eo, eb + 4, htid, barid, myAs, myBs);
    }
}

extern "C" void kernel_launch(void* const* d_in, const int* in_sizes, int n_in,
                              void* d_out, int out_size) {
    (void)in_sizes; (void)n_in; (void)out_size;
    jacobi_fused<<<NCTA, TPB>>>((const float*)d_in[0], (const float*)d_in[1],
                                (float*)d_out);
}

// round 15
// speedup vs baseline: 1.6151x; 1.6151x over previous
#include <cuda_runtime.h>
#include <math.h>

// Spectral solution of 1000 masked-Jacobi steps on 512x512, ONE persistent
// kernel, DST parity butterfly (see R13 header for the math).
// Round 15: REVERT the R14 symmetric barrier (16K pollers saturated L2 and
// starved compute warps: issue 19->13%, +16us). Restore R13's two-hop
// CTA0-aggregated barrier (127 + 127 pollers). KEEP the two sound R14 ideas:
//  - const-operand LDGs issued BEFORE the grid barrier (latency hides under
//    the barrier wait): G2 A=S, G3 B=S, G4 A=STe/STo
//  - W-weight computation after G1 (off the bar1->G1 critical path; still
//    ordered before G3's reads by barriers 2+3)

#define NCTA 128
#define TPB  512
#define HTPB 256
#define GT   (NCTA * TPB)
#define SMS  68                  // smem row stride: 272B = 17*16B
#define CHUNK (16 * SMS)

__device__ float g_Be [512 * 256];      // B even columns
__device__ float g_Bo [512 * 256];      // B odd columns
__device__ float g_S  [128 * 512];      // S[m][c] = sin(pi I(m)(c+1)/511)
__device__ float g_STe[256 * 64];       // STe[k2][i-1] = s_i at grid col 2k2
__device__ float g_STo[256 * 64];       // STo[k2][i-1] = s_i at grid col 2k2+1
__device__ float g_PE [8 * 512 * 64];   // G1 even-parity K-partials
__device__ float g_PO [8 * 512 * 64];   // G1 odd-parity  K-partials
__device__ float g_Cq [16 * 128 * 128]; // G2 K-partials
__device__ float g_U  [4 * 128 * 512];  // G3 K-partials
__device__ float g_W  [128 * 128];      // signed spectral weights
__device__ float2 g_cds[64];            // cos(pi*i/511), i=1..64, double-single
__device__ unsigned g_bar[NCTA + 1];    // [cta]=arrive, [NCTA]=release

__device__ __forceinline__ unsigned ld_acq(const unsigned* p) {
    unsigned v;
    asm volatile("ld.acquire.gpu.u32 %0, [%1];" : "=r"(v) : "l"(p) : "memory");
    return v;
}
__device__ __forceinline__ void st_rel(unsigned* p, unsigned v) {
    asm volatile("st.release.gpu.u32 [%0], %1;" :: "l"(p), "r"(v) : "memory");
}
__device__ __forceinline__ void bar_named(int id) {
    asm volatile("bar.sync %0, %1;" :: "r"(id), "r"(HTPB) : "memory");
}
__device__ __forceinline__ int modeI(int m) { return (m < 64) ? (m + 1) : (574 - m); }

// Two-hop CTA0-aggregated grid barrier (R13 proven): CTA0 threads 1..127
// poll per-CTA arrive flags; all other CTAs poll the single release word.
__device__ __forceinline__ void grid_bar(unsigned ep) {
    __syncthreads();
    const int cta = blockIdx.x, tid = threadIdx.x;
    if (cta == 0) {
        if (tid > 0 && tid < NCTA)
            while (ld_acq(&g_bar[tid]) < ep) { }
        __syncthreads();
        if (tid == 0) st_rel(&g_bar[NCTA], ep);
    } else {
        if (tid == 0) {
            st_rel(&g_bar[cta], ep);
            while (ld_acq(&g_bar[NCTA]) < ep) { }
        }
        __syncthreads();
    }
}

// ---- double-single (two-float) helpers ----
struct DS { float hi, lo; };
__device__ __forceinline__ DS ds_renorm(float s, float e) {
    float hi = s + e;
    float lo = e - (hi - s);
    return DS{hi, lo};
}
__device__ __forceinline__ DS ds_add(DS a, DS b) {
    float s = a.hi + b.hi;
    float v = s - a.hi;
    float e = (a.hi - (s - v)) + (b.hi - v);
    return ds_renorm(s, (e + a.lo) + b.lo);
}
__device__ __forceinline__ DS ds_mul(DS a, DS b) {
    float p = a.hi * b.hi;
    float e = fmaf(a.hi, b.hi, -p);
    e = fmaf(a.hi, b.lo, e);
    e = fmaf(a.lo, b.hi, e);
    return ds_renorm(p, e);
}

// AF: 0 plain A; 1 = (Cq0+..+Cq15) ⊙ W (lda=128)
// BF: 0 plain B; 1 = sum8(PE)+sgn*sum8(PO); 2 = sum4(U_low)+sgn*sum4(U_high)
// STM: 0 plain store; 1 = strided shifted store (row 2*k2+1+eo, col c+1)
// CPRE: 0 = barrier first; 1 = A const (loadA, barrier, loadB);
//       2 = B const (loadB, barrier, loadA)
template<int BM, int TM, int AF, int BF, int STM, int CPRE>
__device__ void gemm_tile(const float* __restrict__ A, int lda,
                          const float* __restrict__ Bop, int ldb,
                          float* __restrict__ Cout, int ldc,
                          int mT, int nT, int kbase, int Klen,
                          float sgn, int eo, unsigned ep,
                          int tid, int barid,
                          float* __restrict__ As, float* __restrict__ Bs) {
    const int tx = tid & 15, ty = tid >> 4;
    const int am = (BM == 64) ? (tid >> 2) : (tid >> 3);
    const int ak = (BM == 64) ? (tid & 3) * 4 : (tid & 7) * 2;
    const int bk = tid >> 4;
    const int bn = (tid & 15) * 2;
    const int nb = (BF == 1) ? ((nT < 64 ? nT : nT - 64) + bn) : 0;

    float4 ra; float2 rb;
    auto loadA = [&](int k0) {
        const int k = kbase + k0 + ak;
        if (AF == 1) {
            const float* p = g_Cq + (mT + am) * 128 + k;
            float2 s = *(const float2*)p;
#pragma unroll
            for (int h = 1; h < 16; h++) {
                float2 c = *(const float2*)(p + h * 16384);
                s.x += c.x; s.y += c.y;
            }
            float2 w = *(const float2*)&g_W[(mT + am) * 128 + k];
            ra.x = s.x * w.x; ra.y = s.y * w.y;
        } else if (BM == 64) {
            ra = *(const float4*)(A + (size_t)(mT + am) * lda + k);
        } else {
            float2 v = *(const float2*)(A + (size_t)(mT + am) * lda + k);
            ra.x = v.x; ra.y = v.y;
        }
    };
    auto loadB = [&](int k0) {
        const int k = kbase + k0 + bk;
        if (BF == 1) {
            const float* pe = g_PE + k * 64 + nb;
            const float* po = g_PO + k * 64 + nb;
            float ex = 0.f, ey = 0.f, ox = 0.f, oy = 0.f;
#pragma unroll
            for (int h = 0; h < 8; h++) {
                float2 e = *(const float2*)(pe + h * 32768);
                float2 o = *(const float2*)(po + h * 32768);
                ex += e.x; ey += e.y; ox += o.x; oy += o.y;
            }
            rb.x = fmaf(sgn, ox, ex); rb.y = fmaf(sgn, oy, ey);
        } else if (BF == 2) {
            const float* pl = g_U + k * 512 + nT + bn;
            float lx = 0.f, ly = 0.f, hx = 0.f, hy = 0.f;
#pragma unroll
            for (int h = 0; h < 4; h++) {
                float2 l  = *(const float2*)(pl + h * 65536);
                float2 hh = *(const float2*)(pl + 64 * 512 + h * 65536);
                lx += l.x; ly += l.y; hx += hh.x; hy += hh.y;
            }
            rb.x = fmaf(sgn, hx, lx); rb.y = fmaf(sgn, hy, ly);
        } else {
            rb = *(const float2*)(Bop + (size_t)k * ldb + nT + bn);
        }
    };
    auto stash = [&](int buf) {
        float* as = As + buf * CHUNK;
        float* bs = Bs + buf * CHUNK;
        as[(ak + 0) * SMS + am] = ra.x;            // A transposed
        as[(ak + 1) * SMS + am] = ra.y;
        if (BM == 64) {
            as[(ak + 2) * SMS + am] = ra.z;
            as[(ak + 3) * SMS + am] = ra.w;
        }
        *(float2*)&bs[bk * SMS + bn] = rb;
    };

    // prologue: const operand's LDGs issued BEFORE the grid barrier so their
    // latency hides under the barrier wait; data operand loaded after.
    if (CPRE == 1)      { loadA(0); grid_bar(ep); loadB(0); }
    else if (CPRE == 2) { loadB(0); grid_bar(ep); loadA(0); }
    else                { grid_bar(ep); loadA(0); loadB(0); }

    float acc[TM][2];
#pragma unroll
    for (int i = 0; i < TM; i++) { acc[i][0] = 0.0f; acc[i][1] = 0.0f; }

    const int nchunk = Klen / 16;
    stash(0);
    bar_named(barid);

    for (int c = 0; c < nchunk; c++) {
        const float* as = As + (c & 1) * CHUNK;
        const float* bs = Bs + (c & 1) * CHUNK;
        if (c + 1 < nchunk) { loadA((c + 1) * 16); loadB((c + 1) * 16); }
#pragma unroll
        for (int kk = 0; kk < 16; kk++) {
            float a[TM];
            if (TM == 4) {
                float4 v = *(const float4*)&as[kk * SMS + ty * 4];
                a[0] = v.x; a[1] = v.y; a[2] = v.z; a[3] = v.w;
            } else {
                float2 v = *(const float2*)&as[kk * SMS + ty * 2];
                a[0] = v.x; a[1] = v.y;
            }
            float2 b = *(const float2*)&bs[kk * SMS + tx * 2];
#pragma unroll
            for (int i = 0; i < TM; i++) {
                acc[i][0] += a[i] * b.x;
                acc[i][1] += a[i] * b.y;
            }
        }
        if (c + 1 < nchunk) stash((c + 1) & 1);
        bar_named(barid);
    }

    if (STM == 1) {
#pragma unroll
        for (int i = 0; i < TM; i++) {
            int k2 = mT + ty * TM + i;
            if (k2 >= 255) continue;
            int rr = 2 * k2 + 1 + eo;              // +1 output shift
#pragma unroll
            for (int j = 0; j < 2; j++) {
                int c2 = nT + tx * 2 + j;
                if (c2 < 510) Cout[rr * 512 + c2 + 1] = acc[i][j];
            }
        }
    } else {
#pragma unroll
        for (int i = 0; i < TM; i++)
            *(float2*)&Cout[(size_t)(mT + ty * TM + i) * ldc + nT + tx * 2] =
                make_float2(acc[i][0], acc[i][1]);
    }
}

__global__ void __launch_bounds__(TPB, 1)
jacobi_fused(const float* __restrict__ X, const float* __restrict__ Y,
             float* __restrict__ out) {
    __shared__ float sx0[6 * 512];
    __shared__ float As[2 * 2 * CHUNK];            // [half][buf]
    __shared__ float Bs[2 * 2 * CHUNK];
    const int cta = blockIdx.x, tid = threadIdx.x;
    const int gtid = cta * TPB + tid;
    const int half = tid >> 8;
    const int htid = tid & 255;
    const int barid = 1 + half;
    float* myAs = As + half * 2 * CHUNK;
    float* myBs = Bs + half * 2 * CHUNK;
    const unsigned eb = __ldcg(&g_bar[NCTA]);      // epoch base (persists)
    const int jid = cta * 2 + half;                // 0..255

    // ---- Stage A+B fused ----
    if (gtid < 64) {                               // ONLY fp64: 64 cospi calls
        double c = cospi((double)(gtid + 1) / 511.0);
        float hi = (float)c;
        float lo = (float)(c - (double)hi);
        g_cds[gtid] = make_float2(hi, lo);
    }
    const int r0 = cta * 4;
    int nrows = 512 - r0; if (nrows > 6) nrows = 6;
    for (int i = tid; i < nrows * 512; i += TPB) {
        int lr = i >> 9, j = i & 511;
        int g = (r0 + lr) * 512 + j;
        float dx = X[g] - 0.5f, dy = Y[g] - 0.5f;
        sx0[i] = expf(-50.0f * (dx * dx + dy * dy));
    }
    __syncthreads();
    for (int i = tid; i < 4 * 512; i += TPB) {     // exact stencil, split cols
        int lk = i >> 9, j = i & 511;
        int k = r0 + lk;
        float v = 0.0f;
        if (k < 510 && j < 510)
            v = 0.25f * (((sx0[lk * 512 + j + 1] + sx0[(lk + 2) * 512 + j + 1])
                          + sx0[(lk + 1) * 512 + j]) + sx0[(lk + 1) * 512 + j + 2]);
        if (j & 1) g_Bo[k * 256 + (j >> 1)] = v;
        else       g_Be[k * 256 + (j >> 1)] = v;
    }
    for (int i = gtid; i < 128 * 512; i += GT) {   // S[m][c]
        int m = i >> 9, c = i & 511;
        float v = 0.0f;
        if (c < 510) {
            int a = (modeI(m) * (c + 1)) % 1022;   // exact reduction
            v = sinpif((float)a * (1.0f / 511.0f));
        }
        g_S[i] = v;
    }
    for (int i = gtid; i < 256 * 64; i += GT) {    // STe/STo
        int k2 = i >> 6, ii = (i & 63) + 1;
        float ve = 0.0f, vo = 0.0f;
        if (k2 < 255) {
            int ae = (ii * (2 * k2 + 1)) % 1022;
            ve = sinpif((float)ae * (1.0f / 511.0f));
            int ao = (ii * (2 * k2 + 2)) % 1022;
            vo = sinpif((float)ao * (1.0f / 511.0f));
        }
        g_STe[i] = ve; g_STo[i] = vo;
    }
    for (int i = gtid; i < 2048; i += GT) {        // out boundary
        int e = i >> 9, t = i & 511;
        if      (e == 0) out[t] = 0.0f;
        else if (e == 1) out[511 * 512 + t] = 0.0f;
        else if (e == 2) out[t * 512] = 0.0f;
        else             out[t * 512 + 511] = 0.0f;
    }

    // ---- G1: PE = Be*STe / PO = Bo*STo (bar eb+1 inside, CPRE=0) ----
    {
        int p = jid & 1, t = (jid >> 1) & 15, h = jid >> 5;
        const float* Aop = p ? g_Bo : g_Be;
        const float* Bop = p ? g_STo : g_STe;
        float* Cop = (p ? g_PO : g_PE) + h * 32768;
        gemm_tile<64, 4, 0, 0, 0, 0>(Aop, 256, Bop, 64, Cop, 64,
                                     (t >> 1) * 64, (t & 1) * 32, h * 32, 32,
                                     0.f, 0, eb + 1, htid, barid, myAs, myBs);
    }

    // ---- W in DS fp32, AFTER G1 (off bar1 critical path; ordered before
    //      G3's reads by barriers eb+2 and eb+3) ----
    for (int i = gtid; i < 128 * 128; i += GT) {
        int m = i >> 7, n = i & 127;
        float2 a2 = g_cds[(m < 64) ? m : (m - 64)];
        float2 b2 = g_cds[(n < 64) ? n : (n - 64)];
        DS cm = (m < 64) ? DS{a2.x, a2.y} : DS{-a2.x, -a2.y};
        DS cn = (n < 64) ? DS{b2.x, b2.y} : DS{-b2.x, -b2.y};
        DS lam = ds_add(cm, cn);
        lam.hi *= 0.5f; lam.lo *= 0.5f;
        DS r{1.0f, 0.0f}, b = lam;
        int e = 999;
        while (e) {
            if (e & 1) r = ds_mul(r, b);
            b = ds_mul(b, b);
            e >>= 1;
        }
        const DS K{1.5318627e-05f, -5.6477107e-13f};   // 4/511^2 split
        r = ds_mul(r, K);
        g_W[i] = r.hi + r.lo;
    }

    // ---- G2: Cq = S * (PE +/- PO fused); A=S const (CPRE=1), bar eb+2 ----
    {
        int t = jid >> 4, h = jid & 15;
        int mT = (t >> 2) * 32, nT = (t & 3) * 32;
        float sgn = (nT < 64) ? 1.0f : -1.0f;
        gemm_tile<32, 2, 0, 1, 0, 1>(g_S, 512, g_PE, 64, g_Cq + h * 16384, 128,
                                     mT, nT, h * 32, 32,
                                     sgn, 0, eb + 2, htid, barid, myAs, myBs);
    }

    // ---- G3: U = ((sum Cq) ⊙ W) * S; B=S const (CPRE=2), bar eb+3 ----
    {
        int t = jid >> 2, h = jid & 3;
        gemm_tile<32, 2, 1, 0, 0, 2>(g_Cq, 128, g_S, 512, g_U + h * 65536, 512,
                                     (t >> 4) * 32, (t & 15) * 32, h * 32, 32,
                                     0.f, 0, eb + 3, htid, barid, myAs, myBs);
    }

    // ---- G4: out_e = STe*(Ul+Uh), out_o = STo*(Ul-Uh); A const, bar eb+4 ----
    {
        int eo = jid >> 7, t = jid & 127;
        const float* Aop = eo ? g_STo : g_STe;
        float sgn = eo ? -1.0f : 1.0f;
        gemm_tile<32, 2, 0, 2, 1, 1>(Aop, 64, g_U, 512, out, 512,
                                     (t >> 4) * 32, (t & 15) * 32, 0, 64,
                                     sgn, eo, eb + 4, htid, barid, myAs, myBs);
    }
}

extern "C" void kernel_launch(void* const* d_in, const int* in_sizes, int n_in,
                              void* d_out, int out_size) {
    (void)in_sizes; (void)n_in; (void)out_size;
    jacobi_fused<<<NCTA, TPB>>>((const float*)d_in[0], (const float*)d_in[1],
                                (float*)d_out);
}